// round 8
// baseline (speedup 1.0000x reference)
#include <cuda_runtime.h>
#include <cuda_fp16.h>
#include <cstdint>

// Problem shape
#define M_TOTAL 16384
#define N_TOTAL 4096
#define K_TOTAL 4096

// GEMM tiling (fp16 elements)
#define BM 128
#define BN 256
#define BK 64
#define STAGES 4
#define ITERS (K_TOTAL / BK)             // 64
#define THREADS 512

#define A_BYTES   (BM * BK * 2)          // 16384
#define B_BYTES   (BN * BK * 2)          // 32768
#define STG_BYTES (A_BYTES + B_BYTES)    // 49152
#define SMEM_TOTAL (STAGES * STG_BYTES)  // 196608

// Static scratch (no allocs). A: [M,4096] fp16 copy of x. W: [N,4096] fp16 (exact).
__device__ __align__(1024) __half g_A[(size_t)M_TOTAL * K_TOTAL];
__device__ __align__(1024) __half g_W[(size_t)N_TOTAL * K_TOTAL];

// ---------------- prologue: one fused conversion kernel ----------------

#define XBLKS 65536   // (M*K/4)/256
#define WBLKS 16384   // (N*K/4)/256

__global__ void convert_all(const float4* __restrict__ x, const int4* __restrict__ wq) {
    int b = blockIdx.x;
    if (b < XBLKS) {
        int i = b * 256 + threadIdx.x;
        float4 v = x[i];
        __half2 h01 = __floats2half2_rn(v.x, v.y);
        __half2 h23 = __floats2half2_rn(v.z, v.w);
        uint2 pv;
        pv.x = *(uint32_t*)&h01;
        pv.y = *(uint32_t*)&h23;
        *(uint2*)&g_A[(size_t)i * 4] = pv;
    } else {
        int i = (b - XBLKS) * 256 + threadIdx.x;
        int4 v = wq[i];
        __half2 h01 = __floats2half2_rn((float)v.x, (float)v.y);
        __half2 h23 = __floats2half2_rn((float)v.z, (float)v.w);
        uint2 pv;
        pv.x = *(uint32_t*)&h01;
        pv.y = *(uint32_t*)&h23;
        *(uint2*)&g_W[(size_t)i * 4] = pv;
    }
}

// ---------------- GEMM ----------------

__device__ __forceinline__ void cp16(uint32_t smem_dst, const void* gsrc) {
    asm volatile("cp.async.cg.shared.global [%0], [%1], 16;"
                 :: "r"(smem_dst), "l"(gsrc));
}

__device__ __forceinline__ void cp_commit() {
    asm volatile("cp.async.commit_group;" ::: "memory");
}

__device__ __forceinline__ void ldsm_x4(uint32_t* r, uint32_t addr) {
    asm volatile("ldmatrix.sync.aligned.m8n8.x4.shared.b16 {%0,%1,%2,%3}, [%4];"
                 : "=r"(r[0]), "=r"(r[1]), "=r"(r[2]), "=r"(r[3]) : "r"(addr));
}

__device__ __forceinline__ void mma_f16(float* c, const uint32_t* a, const uint32_t* b) {
    asm volatile(
        "mma.sync.aligned.m16n8k16.row.col.f32.f16.f16.f32 "
        "{%0,%1,%2,%3}, {%4,%5,%6,%7}, {%8,%9}, {%0,%1,%2,%3};"
        : "+f"(c[0]), "+f"(c[1]), "+f"(c[2]), "+f"(c[3])
        : "r"(a[0]), "r"(a[1]), "r"(a[2]), "r"(a[3]), "r"(b[0]), "r"(b[1]));
}

__global__ void __launch_bounds__(THREADS, 1)
gemm_f16(const float* __restrict__ scale,
         const float* __restrict__ bias,
         float* __restrict__ out)
{
    extern __shared__ __align__(1024) char smem[];
    const uint32_t sb = (uint32_t)__cvta_generic_to_shared(smem);

    const int tid  = threadIdx.x;
    const int lane = tid & 31;
    const int wid  = tid >> 5;         // 16 warps
    const int wm   = wid & 1;          // 2 warp rows (M), 64 rows each
    const int wn   = wid >> 1;         // 8 warp cols (N), 32 cols each
    const int m_cta = blockIdx.y * BM;
    const int n_cta = blockIdx.x * BN;

    // ---- ldmatrix lane address precompute ----
    // A (16x16 tiles, x4): lanes 0-15 -> rows @k0, lanes 16-31 -> same rows @k0+8
    const int arow  = lane & 15;
    const int ahalf = lane >> 4;
    const uint32_t a_xr = (uint32_t)((arow & 7) * 16);
    uint32_t a_off[4];
    #pragma unroll
    for (int mt = 0; mt < 4; mt++)
        a_off[mt] = (uint32_t)((wm * 64 + mt * 16 + arow) * 128);

    // B: x4 covers 16 N rows x k16. lanes 0-7 n0..7@k0, 8-15 n0..7@k0+8,
    //    16-23 n8..15@k0, 24-31 n8..15@k0+8
    const int brow_in = lane & 7;
    const int bkh     = (lane >> 3) & 1;
    const int bn2     = lane >> 4;
    const uint32_t b_xr = (uint32_t)(brow_in * 16);
    uint32_t b_off[2];
    #pragma unroll
    for (int nt2 = 0; nt2 < 2; nt2++)
        b_off[nt2] = (uint32_t)((wn * 32 + nt2 * 16 + bn2 * 8 + brow_in) * 128);

    // ---- producer mapping (cp.async): 512 threads, 16B chunks ----
    const int prow = tid >> 3;         // 64 rows per pass
    const int chnk = tid & 7;          // 8 x 16B chunks per 128B row
    const uint32_t sw_st = (uint32_t)(chnk * 16);

    auto load_slab = [&](int kit, int s) {
        const uint32_t st = sb + s * STG_BYTES;
        const __half* aG = g_A + (size_t)m_cta * K_TOTAL + kit * BK;
        const __half* bG = g_W + (size_t)n_cta * K_TOTAL + kit * BK;
        #pragma unroll
        for (int j = 0; j < 2; j++) {
            int row = prow + j * 64;
            uint32_t dst = st + row * 128 + (sw_st ^ ((row & 7) * 16));
            cp16(dst, aG + (size_t)row * K_TOTAL + chnk * 8);
        }
        #pragma unroll
        for (int j = 0; j < 4; j++) {
            int row = prow + j * 64;
            uint32_t dst = st + A_BYTES + row * 128 + (sw_st ^ ((row & 7) * 16));
            cp16(dst, bG + (size_t)row * K_TOTAL + chnk * 8);
        }
    };

    float acc[4][4][4];
    #pragma unroll
    for (int mt = 0; mt < 4; mt++)
        #pragma unroll
        for (int nt = 0; nt < 4; nt++)
            #pragma unroll
            for (int j = 0; j < 4; j++)
                acc[mt][nt][j] = 0.0f;

    #pragma unroll
    for (int s = 0; s < STAGES - 1; s++) {
        load_slab(s, s);
        cp_commit();
    }

    for (int i = 0; i < ITERS; i++) {
        asm volatile("cp.async.wait_group %0;" :: "n"(STAGES - 2) : "memory");
        __syncthreads();

        if (i + STAGES - 1 < ITERS)
            load_slab(i + STAGES - 1, (i + STAGES - 1) & (STAGES - 1));
        cp_commit();

        const uint32_t abase = sb + (i & (STAGES - 1)) * STG_BYTES;
        const uint32_t bbase = abase + A_BYTES;

        #pragma unroll
        for (int ks = 0; ks < 4; ks++) {
            uint32_t af[4][4];
            const uint32_t acol = (uint32_t)(ks * 32 + ahalf * 16);
            #pragma unroll
            for (int mt = 0; mt < 4; mt++)
                ldsm_x4(af[mt], abase + a_off[mt] + (acol ^ a_xr));

            uint32_t bf[4][2];
            const uint32_t bcol = (uint32_t)(ks * 32 + bkh * 16);
            #pragma unroll
            for (int nt2 = 0; nt2 < 2; nt2++) {
                uint32_t r[4];
                ldsm_x4(r, bbase + b_off[nt2] + (bcol ^ b_xr));
                bf[2 * nt2][0] = r[0];     bf[2 * nt2][1] = r[1];
                bf[2 * nt2 + 1][0] = r[2]; bf[2 * nt2 + 1][1] = r[3];
            }

            #pragma unroll
            for (int mt = 0; mt < 4; mt++)
                #pragma unroll
                for (int nt = 0; nt < 4; nt++)
                    mma_f16(acc[mt][nt], af[mt], bf[nt]);
        }
    }

    // epilogue: y = scale * acc + bias
    const float sc = __ldg(scale);
    const int r_lo = lane >> 2;
    #pragma unroll
    for (int mt = 0; mt < 4; mt++) {
        const int m0 = m_cta + wm * 64 + mt * 16 + r_lo;
        #pragma unroll
        for (int nt = 0; nt < 4; nt++) {
            const int n0 = n_cta + wn * 32 + nt * 8 + (lane & 3) * 2;
            const float b0 = __ldg(bias + n0);
            const float b1 = __ldg(bias + n0 + 1);
            float2 v0, v1;
            v0.x = fmaf(sc, acc[mt][nt][0], b0);
            v0.y = fmaf(sc, acc[mt][nt][1], b1);
            v1.x = fmaf(sc, acc[mt][nt][2], b0);
            v1.y = fmaf(sc, acc[mt][nt][3], b1);
            *(float2*)(out + (size_t)m0 * N_TOTAL + n0)       = v0;
            *(float2*)(out + (size_t)(m0 + 8) * N_TOTAL + n0) = v1;
        }
    }
}

// ---------------- host ----------------

extern "C" void kernel_launch(void* const* d_in, const int* in_sizes, int n_in,
                              void* d_out, int out_size)
{
    const float* x     = (const float*)d_in[0];
    const int*   wq    = (const int*)  d_in[1];
    const float* scale = (const float*)d_in[2];
    const float* bias  = (const float*)d_in[3];
    float*       out   = (float*)d_out;

    convert_all<<<XBLKS + WBLKS, 256>>>((const float4*)x, (const int4*)wq);

    static bool attr_set = false;
    if (!attr_set) {
        cudaFuncSetAttribute(gemm_f16,
                             cudaFuncAttributeMaxDynamicSharedMemorySize, SMEM_TOTAL);
        attr_set = true;
    }

    dim3 grid(N_TOTAL / BN, M_TOTAL / BM);      // (16, 128)
    gemm_f16<<<grid, THREADS, SMEM_TOTAL>>>(scale, bias, out);
}

// round 10
// speedup vs baseline: 1.1068x; 1.1068x over previous
#include <cuda_runtime.h>
#include <cuda_fp16.h>
#include <cstdint>

// Problem shape
#define M_TOTAL 16384
#define N_TOTAL 4096
#define K_TOTAL 4096

// GEMM tiling (fp16 elements)
#define BM 128
#define BN 128
#define BK 64
#define STAGES 3
#define ITERS (K_TOTAL / BK)             // 64
#define THREADS 256

#define A_BYTES   (BM * BK * 2)          // 16384
#define B_BYTES   (BN * BK * 2)          // 16384
#define STG_BYTES (A_BYTES + B_BYTES)    // 32768
#define SMEM_TOTAL (STAGES * STG_BYTES)  // 98304

// Static scratch (no allocs). A: [M,4096] fp16 copy of x. W: [N,4096] fp16 (exact).
__device__ __align__(1024) __half g_A[(size_t)M_TOTAL * K_TOTAL];
__device__ __align__(1024) __half g_W[(size_t)N_TOTAL * K_TOTAL];

// ---------------- prologue: one fused conversion kernel ----------------

#define XBLKS 65536   // (M*K/4)/256
#define WBLKS 16384   // (N*K/4)/256

__global__ void convert_all(const float4* __restrict__ x, const int4* __restrict__ wq) {
    int b = blockIdx.x;
    if (b < XBLKS) {
        int i = b * 256 + threadIdx.x;
        float4 v = x[i];
        __half2 h01 = __floats2half2_rn(v.x, v.y);
        __half2 h23 = __floats2half2_rn(v.z, v.w);
        uint2 pv;
        pv.x = *(uint32_t*)&h01;
        pv.y = *(uint32_t*)&h23;
        *(uint2*)&g_A[(size_t)i * 4] = pv;
    } else {
        int i = (b - XBLKS) * 256 + threadIdx.x;
        int4 v = wq[i];
        __half2 h01 = __floats2half2_rn((float)v.x, (float)v.y);
        __half2 h23 = __floats2half2_rn((float)v.z, (float)v.w);
        uint2 pv;
        pv.x = *(uint32_t*)&h01;
        pv.y = *(uint32_t*)&h23;
        *(uint2*)&g_W[(size_t)i * 4] = pv;
    }
}

// ---------------- GEMM ----------------

__device__ __forceinline__ void cp16(uint32_t smem_dst, const void* gsrc) {
    asm volatile("cp.async.cg.shared.global [%0], [%1], 16;"
                 :: "r"(smem_dst), "l"(gsrc));
}

__device__ __forceinline__ void cp_commit() {
    asm volatile("cp.async.commit_group;" ::: "memory");
}

__device__ __forceinline__ void ldsm_x4(uint32_t* r, uint32_t addr) {
    asm volatile("ldmatrix.sync.aligned.m8n8.x4.shared.b16 {%0,%1,%2,%3}, [%4];"
                 : "=r"(r[0]), "=r"(r[1]), "=r"(r[2]), "=r"(r[3]) : "r"(addr));
}

__device__ __forceinline__ void mma_f16(float* c, const uint32_t* a, const uint32_t* b) {
    asm volatile(
        "mma.sync.aligned.m16n8k16.row.col.f32.f16.f16.f32 "
        "{%0,%1,%2,%3}, {%4,%5,%6,%7}, {%8,%9}, {%0,%1,%2,%3};"
        : "+f"(c[0]), "+f"(c[1]), "+f"(c[2]), "+f"(c[3])
        : "r"(a[0]), "r"(a[1]), "r"(a[2]), "r"(a[3]), "r"(b[0]), "r"(b[1]));
}

__global__ void __launch_bounds__(THREADS, 2)
gemm_f16(const float* __restrict__ scale,
         const float* __restrict__ bias,
         float* __restrict__ out)
{
    extern __shared__ __align__(1024) char smem[];
    const uint32_t sb = (uint32_t)__cvta_generic_to_shared(smem);

    const int tid  = threadIdx.x;
    const int lane = tid & 31;
    const int wid  = tid >> 5;         // 8 warps
    const int wm   = wid & 1;          // 2 warp rows (M), 64 rows each
    const int wn   = wid >> 1;         // 4 warp cols (N), 32 cols each
    const int m_cta = blockIdx.y * BM;
    const int n_cta = blockIdx.x * BN;

    // ---- ldmatrix lane address precompute ----
    // A (16x16 tiles, x4): lanes 0-15 -> rows @k0, lanes 16-31 -> same rows @k0+8
    const int arow  = lane & 15;
    const int ahalf = lane >> 4;
    const uint32_t a_xr = (uint32_t)((arow & 7) * 16);
    uint32_t a_off[4];
    #pragma unroll
    for (int mt = 0; mt < 4; mt++)
        a_off[mt] = (uint32_t)((wm * 64 + mt * 16 + arow) * 128);

    // B: x4 covers 16 N rows x k16. lanes 0-7 n0..7@k0, 8-15 n0..7@k0+8,
    //    16-23 n8..15@k0, 24-31 n8..15@k0+8
    const int brow_in = lane & 7;
    const int bkh     = (lane >> 3) & 1;
    const int bn2     = lane >> 4;
    const uint32_t b_xr = (uint32_t)(brow_in * 16);
    uint32_t b_off[2];
    #pragma unroll
    for (int nt2 = 0; nt2 < 2; nt2++)
        b_off[nt2] = (uint32_t)((wn * 32 + nt2 * 16 + bn2 * 8 + brow_in) * 128);

    // ---- producer mapping (cp.async): 256 threads, 16B chunks ----
    const int prow = tid >> 3;         // 32 rows per pass
    const int chnk = tid & 7;          // 8 x 16B chunks per 128B row
    const uint32_t sw_st = (uint32_t)(chnk * 16);

    auto load_slab = [&](int kit, int s) {
        const uint32_t st = sb + s * STG_BYTES;
        const __half* aG = g_A + (size_t)m_cta * K_TOTAL + kit * BK;
        const __half* bG = g_W + (size_t)n_cta * K_TOTAL + kit * BK;
        #pragma unroll
        for (int j = 0; j < 4; j++) {
            int row = prow + j * 32;
            uint32_t dst = st + row * 128 + (sw_st ^ ((row & 7) * 16));
            cp16(dst, aG + (size_t)row * K_TOTAL + chnk * 8);
        }
        #pragma unroll
        for (int j = 0; j < 4; j++) {
            int row = prow + j * 32;
            uint32_t dst = st + A_BYTES + row * 128 + (sw_st ^ ((row & 7) * 16));
            cp16(dst, bG + (size_t)row * K_TOTAL + chnk * 8);
        }
    };

    float acc[4][4][4];
    #pragma unroll
    for (int mt = 0; mt < 4; mt++)
        #pragma unroll
        for (int nt = 0; nt < 4; nt++)
            #pragma unroll
            for (int j = 0; j < 4; j++)
                acc[mt][nt][j] = 0.0f;

    #pragma unroll
    for (int s = 0; s < STAGES - 1; s++) {
        load_slab(s, s);
        cp_commit();
    }

    int stage = 0;
    for (int i = 0; i < ITERS; i++) {
        asm volatile("cp.async.wait_group %0;" :: "n"(STAGES - 2) : "memory");
        __syncthreads();

        if (i + STAGES - 1 < ITERS) {
            int ps = stage + (STAGES - 1);
            if (ps >= STAGES) ps -= STAGES;
            load_slab(i + STAGES - 1, ps);
        }
        cp_commit();

        const uint32_t abase = sb + stage * STG_BYTES;
        const uint32_t bbase = abase + A_BYTES;
        if (++stage == STAGES) stage = 0;

        #pragma unroll
        for (int ks = 0; ks < 4; ks++) {
            uint32_t af[4][4];
            const uint32_t acol = (uint32_t)(ks * 32 + ahalf * 16);
            #pragma unroll
            for (int mt = 0; mt < 4; mt++)
                ldsm_x4(af[mt], abase + a_off[mt] + (acol ^ a_xr));

            uint32_t bf[4][2];
            const uint32_t bcol = (uint32_t)(ks * 32 + bkh * 16);
            #pragma unroll
            for (int nt2 = 0; nt2 < 2; nt2++) {
                uint32_t r[4];
                ldsm_x4(r, bbase + b_off[nt2] + (bcol ^ b_xr));
                bf[2 * nt2][0] = r[0];     bf[2 * nt2][1] = r[1];
                bf[2 * nt2 + 1][0] = r[2]; bf[2 * nt2 + 1][1] = r[3];
            }

            #pragma unroll
            for (int mt = 0; mt < 4; mt++)
                #pragma unroll
                for (int nt = 0; nt < 4; nt++)
                    mma_f16(acc[mt][nt], af[mt], bf[nt]);
        }
    }

    // epilogue: y = scale * acc + bias
    const float sc = __ldg(scale);
    const int r_lo = lane >> 2;
    #pragma unroll
    for (int mt = 0; mt < 4; mt++) {
        const int m0 = m_cta + wm * 64 + mt * 16 + r_lo;
        #pragma unroll
        for (int nt = 0; nt < 4; nt++) {
            const int n0 = n_cta + wn * 32 + nt * 8 + (lane & 3) * 2;
            const float b0 = __ldg(bias + n0);
            const float b1 = __ldg(bias + n0 + 1);
            float2 v0, v1;
            v0.x = fmaf(sc, acc[mt][nt][0], b0);
            v0.y = fmaf(sc, acc[mt][nt][1], b1);
            v1.x = fmaf(sc, acc[mt][nt][2], b0);
            v1.y = fmaf(sc, acc[mt][nt][3], b1);
            *(float2*)(out + (size_t)m0 * N_TOTAL + n0)       = v0;
            *(float2*)(out + (size_t)(m0 + 8) * N_TOTAL + n0) = v1;
        }
    }
}

// ---------------- host ----------------

extern "C" void kernel_launch(void* const* d_in, const int* in_sizes, int n_in,
                              void* d_out, int out_size)
{
    const float* x     = (const float*)d_in[0];
    const int*   wq    = (const int*)  d_in[1];
    const float* scale = (const float*)d_in[2];
    const float* bias  = (const float*)d_in[3];
    float*       out   = (float*)d_out;

    convert_all<<<XBLKS + WBLKS, 256>>>((const float4*)x, (const int4*)wq);

    static bool attr_set = false;
    if (!attr_set) {
        cudaFuncSetAttribute(gemm_f16,
                             cudaFuncAttributeMaxDynamicSharedMemorySize, SMEM_TOTAL);
        attr_set = true;
    }

    dim3 grid(N_TOTAL / BN, M_TOTAL / BM);      // (32, 128)
    gemm_f16<<<grid, THREADS, SMEM_TOTAL>>>(scale, bias, out);
}

// round 11
// speedup vs baseline: 1.1733x; 1.0601x over previous
#include <cuda_runtime.h>
#include <cuda_fp16.h>
#include <cstdint>

// Problem shape
#define M_TOTAL 16384
#define N_TOTAL 4096
#define K_TOTAL 4096

// GEMM tiling (fp16 elements)
#define BM 128
#define BN 128
#define BK 64
#define STAGES 3
#define ITERS (K_TOTAL / BK)             // 64
#define THREADS 128

#define A_BYTES   (BM * BK * 2)          // 16384
#define B_BYTES   (BN * BK * 2)          // 16384
#define STG_BYTES (A_BYTES + B_BYTES)    // 32768
#define SMEM_TOTAL (STAGES * STG_BYTES)  // 98304

// Static scratch (no allocs). A: [M,4096] fp16 copy of x. W: [N,4096] fp16 (exact).
__device__ __align__(1024) __half g_A[(size_t)M_TOTAL * K_TOTAL];
__device__ __align__(1024) __half g_W[(size_t)N_TOTAL * K_TOTAL];

// ---------------- prologue: one fused conversion kernel ----------------

#define XBLKS 65536   // (M*K/4)/256
#define WBLKS 16384   // (N*K/4)/256

__global__ void convert_all(const float4* __restrict__ x, const int4* __restrict__ wq) {
    int b = blockIdx.x;
    if (b < XBLKS) {
        int i = b * 256 + threadIdx.x;
        float4 v = x[i];
        __half2 h01 = __floats2half2_rn(v.x, v.y);
        __half2 h23 = __floats2half2_rn(v.z, v.w);
        uint2 pv;
        pv.x = *(uint32_t*)&h01;
        pv.y = *(uint32_t*)&h23;
        *(uint2*)&g_A[(size_t)i * 4] = pv;
    } else {
        int i = (b - XBLKS) * 256 + threadIdx.x;
        int4 v = wq[i];
        __half2 h01 = __floats2half2_rn((float)v.x, (float)v.y);
        __half2 h23 = __floats2half2_rn((float)v.z, (float)v.w);
        uint2 pv;
        pv.x = *(uint32_t*)&h01;
        pv.y = *(uint32_t*)&h23;
        *(uint2*)&g_W[(size_t)i * 4] = pv;
    }
}

// ---------------- GEMM ----------------

__device__ __forceinline__ void cp16(uint32_t smem_dst, const void* gsrc) {
    asm volatile("cp.async.cg.shared.global [%0], [%1], 16;"
                 :: "r"(smem_dst), "l"(gsrc));
}

__device__ __forceinline__ void cp_commit() {
    asm volatile("cp.async.commit_group;" ::: "memory");
}

__device__ __forceinline__ void ldsm_x4(uint32_t* r, uint32_t addr) {
    asm volatile("ldmatrix.sync.aligned.m8n8.x4.shared.b16 {%0,%1,%2,%3}, [%4];"
                 : "=r"(r[0]), "=r"(r[1]), "=r"(r[2]), "=r"(r[3]) : "r"(addr));
}

__device__ __forceinline__ void mma_f16(float* c, const uint32_t* a, const uint32_t* b) {
    asm volatile(
        "mma.sync.aligned.m16n8k16.row.col.f32.f16.f16.f32 "
        "{%0,%1,%2,%3}, {%4,%5,%6,%7}, {%8,%9}, {%0,%1,%2,%3};"
        : "+f"(c[0]), "+f"(c[1]), "+f"(c[2]), "+f"(c[3])
        : "r"(a[0]), "r"(a[1]), "r"(a[2]), "r"(a[3]), "r"(b[0]), "r"(b[1]));
}

__global__ void __launch_bounds__(THREADS, 2)
gemm_f16(const float* __restrict__ scale,
         const float* __restrict__ bias,
         float* __restrict__ out)
{
    extern __shared__ __align__(1024) char smem[];
    const uint32_t sb = (uint32_t)__cvta_generic_to_shared(smem);

    const int tid  = threadIdx.x;
    const int lane = tid & 31;
    const int wid  = tid >> 5;         // 4 warps
    const int wm   = wid & 1;          // 2 warp rows (M), 64 rows each
    const int wn   = wid >> 1;         // 2 warp cols (N), 64 cols each
    const int m_cta = blockIdx.y * BM;
    const int n_cta = blockIdx.x * BN;

    // ---- ldmatrix lane address precompute ----
    // A (16x16 tiles, x4): lanes 0-15 -> rows @k0, lanes 16-31 -> same rows @k0+8
    const int arow  = lane & 15;
    const int ahalf = lane >> 4;
    const uint32_t a_xr = (uint32_t)((arow & 7) * 16);
    uint32_t a_off[4];
    #pragma unroll
    for (int mt = 0; mt < 4; mt++)
        a_off[mt] = (uint32_t)((wm * 64 + mt * 16 + arow) * 128);

    // B: x4 covers 16 N rows x k16. lanes 0-7 n0..7@k0, 8-15 n0..7@k0+8,
    //    16-23 n8..15@k0, 24-31 n8..15@k0+8
    const int brow_in = lane & 7;
    const int bkh     = (lane >> 3) & 1;
    const int bn2     = lane >> 4;
    const uint32_t b_xr = (uint32_t)(brow_in * 16);
    uint32_t b_off[4];
    #pragma unroll
    for (int nt2 = 0; nt2 < 4; nt2++)
        b_off[nt2] = (uint32_t)((wn * 64 + nt2 * 16 + bn2 * 8 + brow_in) * 128);

    // ---- producer mapping (cp.async): 128 threads, 16B chunks ----
    const int prow = tid >> 3;         // 16 rows per pass
    const int chnk = tid & 7;          // 8 x 16B chunks per 128B row
    const uint32_t sw_st = (uint32_t)(chnk * 16);

    auto load_slab = [&](int kit, int s) {
        const uint32_t st = sb + s * STG_BYTES;
        const __half* aG = g_A + (size_t)m_cta * K_TOTAL + kit * BK;
        const __half* bG = g_W + (size_t)n_cta * K_TOTAL + kit * BK;
        #pragma unroll
        for (int j = 0; j < 8; j++) {
            int row = prow + j * 16;
            uint32_t dst = st + row * 128 + (sw_st ^ ((row & 7) * 16));
            cp16(dst, aG + (size_t)row * K_TOTAL + chnk * 8);
        }
        #pragma unroll
        for (int j = 0; j < 8; j++) {
            int row = prow + j * 16;
            uint32_t dst = st + A_BYTES + row * 128 + (sw_st ^ ((row & 7) * 16));
            cp16(dst, bG + (size_t)row * K_TOTAL + chnk * 8);
        }
    };

    float acc[4][8][4];
    #pragma unroll
    for (int mt = 0; mt < 4; mt++)
        #pragma unroll
        for (int nt = 0; nt < 8; nt++)
            #pragma unroll
            for (int j = 0; j < 4; j++)
                acc[mt][nt][j] = 0.0f;

    #pragma unroll
    for (int s = 0; s < STAGES - 1; s++) {
        load_slab(s, s);
        cp_commit();
    }

    uint32_t af[2][4][4];
    uint32_t bf[2][8][2];

    int stage = 0;
    for (int i = 0; i < ITERS; i++) {
        asm volatile("cp.async.wait_group %0;" :: "n"(STAGES - 2) : "memory");
        __syncthreads();

        if (i + STAGES - 1 < ITERS) {
            int ps = stage + (STAGES - 1);
            if (ps >= STAGES) ps -= STAGES;
            load_slab(i + STAGES - 1, ps);
        }
        cp_commit();

        const uint32_t abase = sb + stage * STG_BYTES;
        const uint32_t bbase = abase + A_BYTES;
        if (++stage == STAGES) stage = 0;

        // prime fragments for ks = 0
        {
            const uint32_t acol = (uint32_t)(ahalf * 16);
            #pragma unroll
            for (int mt = 0; mt < 4; mt++)
                ldsm_x4(af[0][mt], abase + a_off[mt] + (acol ^ a_xr));
            const uint32_t bcol = (uint32_t)(bkh * 16);
            #pragma unroll
            for (int nt2 = 0; nt2 < 4; nt2++) {
                uint32_t r[4];
                ldsm_x4(r, bbase + b_off[nt2] + (bcol ^ b_xr));
                bf[0][2 * nt2][0] = r[0];     bf[0][2 * nt2][1] = r[1];
                bf[0][2 * nt2 + 1][0] = r[2]; bf[0][2 * nt2 + 1][1] = r[3];
            }
        }

        #pragma unroll
        for (int ks = 0; ks < 4; ks++) {
            const int cur = ks & 1, nxt = cur ^ 1;
            if (ks < 3) {   // prefetch next k-sub-step during this one's MMAs
                const uint32_t acol = (uint32_t)((ks + 1) * 32 + ahalf * 16);
                #pragma unroll
                for (int mt = 0; mt < 4; mt++)
                    ldsm_x4(af[nxt][mt], abase + a_off[mt] + (acol ^ a_xr));
                const uint32_t bcol = (uint32_t)((ks + 1) * 32 + bkh * 16);
                #pragma unroll
                for (int nt2 = 0; nt2 < 4; nt2++) {
                    uint32_t r[4];
                    ldsm_x4(r, bbase + b_off[nt2] + (bcol ^ b_xr));
                    bf[nxt][2 * nt2][0] = r[0];     bf[nxt][2 * nt2][1] = r[1];
                    bf[nxt][2 * nt2 + 1][0] = r[2]; bf[nxt][2 * nt2 + 1][1] = r[3];
                }
            }
            #pragma unroll
            for (int mt = 0; mt < 4; mt++)
                #pragma unroll
                for (int nt = 0; nt < 8; nt++)
                    mma_f16(acc[mt][nt], af[cur][mt], bf[cur][nt]);
        }
    }

    // epilogue: y = scale * acc + bias
    const float sc = __ldg(scale);
    const int r_lo = lane >> 2;
    #pragma unroll
    for (int mt = 0; mt < 4; mt++) {
        const int m0 = m_cta + wm * 64 + mt * 16 + r_lo;
        #pragma unroll
        for (int nt = 0; nt < 8; nt++) {
            const int n0 = n_cta + wn * 64 + nt * 8 + (lane & 3) * 2;
            const float b0 = __ldg(bias + n0);
            const float b1 = __ldg(bias + n0 + 1);
            float2 v0, v1;
            v0.x = fmaf(sc, acc[mt][nt][0], b0);
            v0.y = fmaf(sc, acc[mt][nt][1], b1);
            v1.x = fmaf(sc, acc[mt][nt][2], b0);
            v1.y = fmaf(sc, acc[mt][nt][3], b1);
            *(float2*)(out + (size_t)m0 * N_TOTAL + n0)       = v0;
            *(float2*)(out + (size_t)(m0 + 8) * N_TOTAL + n0) = v1;
        }
    }
}

// ---------------- host ----------------

extern "C" void kernel_launch(void* const* d_in, const int* in_sizes, int n_in,
                              void* d_out, int out_size)
{
    const float* x     = (const float*)d_in[0];
    const int*   wq    = (const int*)  d_in[1];
    const float* scale = (const float*)d_in[2];
    const float* bias  = (const float*)d_in[3];
    float*       out   = (float*)d_out;

    convert_all<<<XBLKS + WBLKS, 256>>>((const float4*)x, (const int4*)wq);

    static bool attr_set = false;
    if (!attr_set) {
        cudaFuncSetAttribute(gemm_f16,
                             cudaFuncAttributeMaxDynamicSharedMemorySize, SMEM_TOTAL);
        attr_set = true;
    }

    dim3 grid(N_TOTAL / BN, M_TOTAL / BM);      // (32, 128)
    gemm_f16<<<grid, THREADS, SMEM_TOTAL>>>(scale, bias, out);
}

// round 13
// speedup vs baseline: 1.3015x; 1.1093x over previous
#include <cuda_runtime.h>
#include <cuda_fp16.h>
#include <cstdint>

// Problem shape
#define M_TOTAL 16384
#define N_TOTAL 4096
#define K_TOTAL 4096

// GEMM tiling (fp16 elements)
#define BM 128
#define BN 128
#define BK 64
#define STAGES 3
#define ITERS (K_TOTAL / BK)             // 64
#define THREADS 128

#define A_BYTES   (BM * BK * 2)          // 16384
#define B_BYTES   (BN * BK * 2)          // 16384
#define STG_BYTES (A_BYTES + B_BYTES)    // 32768
#define SMEM_TOTAL (STAGES * STG_BYTES)  // 98304

// Static scratch (no allocs). A: [M,4096] fp16 copy of x. W: [N,4096] fp16 (exact).
__device__ __align__(1024) __half g_A[(size_t)M_TOTAL * K_TOTAL];
__device__ __align__(1024) __half g_W[(size_t)N_TOTAL * K_TOTAL];

// ---------------- prologue: one fused conversion kernel ----------------

#define XBLKS 65536   // (M*K/4)/256
#define WBLKS 16384   // (N*K/4)/256

__global__ void convert_all(const float4* __restrict__ x, const int4* __restrict__ wq) {
    int b = blockIdx.x;
    if (b < XBLKS) {
        int i = b * 256 + threadIdx.x;
        float4 v = x[i];
        __half2 h01 = __floats2half2_rn(v.x, v.y);
        __half2 h23 = __floats2half2_rn(v.z, v.w);
        uint2 pv;
        pv.x = *(uint32_t*)&h01;
        pv.y = *(uint32_t*)&h23;
        *(uint2*)&g_A[(size_t)i * 4] = pv;
    } else {
        int i = (b - XBLKS) * 256 + threadIdx.x;
        int4 v = wq[i];
        __half2 h01 = __floats2half2_rn((float)v.x, (float)v.y);
        __half2 h23 = __floats2half2_rn((float)v.z, (float)v.w);
        uint2 pv;
        pv.x = *(uint32_t*)&h01;
        pv.y = *(uint32_t*)&h23;
        *(uint2*)&g_W[(size_t)i * 4] = pv;
    }
}

// ---------------- GEMM ----------------

__device__ __forceinline__ void cp16(uint32_t smem_dst, const void* gsrc) {
    asm volatile("cp.async.cg.shared.global [%0], [%1], 16;"
                 :: "r"(smem_dst), "l"(gsrc));
}

__device__ __forceinline__ void cp_commit() {
    asm volatile("cp.async.commit_group;" ::: "memory");
}

__device__ __forceinline__ void ldsm_x4(uint32_t* r, uint32_t addr) {
    asm volatile("ldmatrix.sync.aligned.m8n8.x4.shared.b16 {%0,%1,%2,%3}, [%4];"
                 : "=r"(r[0]), "=r"(r[1]), "=r"(r[2]), "=r"(r[3]) : "r"(addr));
}

__device__ __forceinline__ void mma_f16(float* c, const uint32_t* a, const uint32_t* b) {
    asm volatile(
        "mma.sync.aligned.m16n8k16.row.col.f32.f16.f16.f32 "
        "{%0,%1,%2,%3}, {%4,%5,%6,%7}, {%8,%9}, {%0,%1,%2,%3};"
        : "+f"(c[0]), "+f"(c[1]), "+f"(c[2]), "+f"(c[3])
        : "r"(a[0]), "r"(a[1]), "r"(a[2]), "r"(a[3]), "r"(b[0]), "r"(b[1]));
}

__global__ void __launch_bounds__(THREADS, 2)
gemm_f16(const float* __restrict__ scale,
         const float* __restrict__ bias,
         float* __restrict__ out)
{
    extern __shared__ __align__(1024) char smem[];
    const uint32_t sb = (uint32_t)__cvta_generic_to_shared(smem);

    const int tid  = threadIdx.x;
    const int lane = tid & 31;
    const int wid  = tid >> 5;         // 4 warps
    const int wm   = wid & 1;          // 2 warp rows (M), 64 rows each
    const int wn   = wid >> 1;         // 2 warp cols (N), 64 cols each
    const int m_cta = blockIdx.y * BM;
    const int n_cta = blockIdx.x * BN;

    // ---- ldmatrix lane address precompute ----
    const int arow  = lane & 15;
    const int ahalf = lane >> 4;
    const uint32_t a_xr = (uint32_t)((arow & 7) * 16);
    uint32_t a_off[4];
    #pragma unroll
    for (int mt = 0; mt < 4; mt++)
        a_off[mt] = (uint32_t)((wm * 64 + mt * 16 + arow) * 128);

    const int brow_in = lane & 7;
    const int bkh     = (lane >> 3) & 1;
    const int bn2     = lane >> 4;
    const uint32_t b_xr = (uint32_t)(brow_in * 16);
    uint32_t b_off[4];
    #pragma unroll
    for (int nt2 = 0; nt2 < 4; nt2++)
        b_off[nt2] = (uint32_t)((wn * 64 + nt2 * 16 + bn2 * 8 + brow_in) * 128);

    // ---- producer mapping (cp.async): 128 threads, 16B chunks ----
    const int prow = tid >> 3;         // 16 rows per pass
    const int chnk = tid & 7;
    const uint32_t sw_st = (uint32_t)(chnk * 16);

    auto load_slab = [&](int kit, int s) {
        const uint32_t st = sb + s * STG_BYTES;
        const __half* aG = g_A + (size_t)m_cta * K_TOTAL + kit * BK;
        const __half* bG = g_W + (size_t)n_cta * K_TOTAL + kit * BK;
        #pragma unroll
        for (int j = 0; j < 8; j++) {
            int row = prow + j * 16;
            uint32_t dst = st + row * 128 + (sw_st ^ ((row & 7) * 16));
            cp16(dst, aG + (size_t)row * K_TOTAL + chnk * 8);
        }
        #pragma unroll
        for (int j = 0; j < 8; j++) {
            int row = prow + j * 16;
            uint32_t dst = st + A_BYTES + row * 128 + (sw_st ^ ((row & 7) * 16));
            cp16(dst, bG + (size_t)row * K_TOTAL + chnk * 8);
        }
    };

    // fragment loader: buffer <- (stage base, k-sub-step)
    uint32_t af[2][4][4];
    uint32_t bf[2][8][2];
    auto load_frags = [&](int buf, uint32_t abase, int ks) {
        const uint32_t acol = (uint32_t)(ks * 32 + ahalf * 16);
        #pragma unroll
        for (int mt = 0; mt < 4; mt++)
            ldsm_x4(af[buf][mt], abase + a_off[mt] + (acol ^ a_xr));
        const uint32_t bbase = abase + A_BYTES;
        const uint32_t bcol = (uint32_t)(ks * 32 + bkh * 16);
        #pragma unroll
        for (int nt2 = 0; nt2 < 4; nt2++) {
            uint32_t r[4];
            ldsm_x4(r, bbase + b_off[nt2] + (bcol ^ b_xr));
            bf[buf][2 * nt2][0] = r[0];     bf[buf][2 * nt2][1] = r[1];
            bf[buf][2 * nt2 + 1][0] = r[2]; bf[buf][2 * nt2 + 1][1] = r[3];
        }
    };

    float acc[4][8][4];
    #pragma unroll
    for (int mt = 0; mt < 4; mt++)
        #pragma unroll
        for (int nt = 0; nt < 8; nt++)
            #pragma unroll
            for (int j = 0; j < 4; j++)
                acc[mt][nt][j] = 0.0f;

    // prologue: stages 0,1 in flight; wait all; prime iter-0 ks-0 fragments
    load_slab(0, 0); cp_commit();
    load_slab(1, 1); cp_commit();
    asm volatile("cp.async.wait_group 0;" ::: "memory");
    __syncthreads();
    load_frags(0, sb + 0 * STG_BYTES, 0);

    int stage = 0;                      // stage holding slab i
    for (int i = 0; i < ITERS; i++) {
        const uint32_t abase = sb + stage * STG_BYTES;
        int nstage = stage + 1; if (nstage == STAGES) nstage = 0;
        int wstage = nstage + 1; if (wstage == STAGES) wstage = 0;  // (i+2)%3

        #pragma unroll
        for (int ks = 0; ks < 4; ks++) {
            const int cur = ks & 1, nxt = cur ^ 1;
            if (ks < 3) {
                load_frags(nxt, abase, ks + 1);
            } else if (i + 1 < ITERS) {
                // cross-iteration prefetch: next iter's ks=0 from stage (i+1)%3
                load_frags(nxt, sb + nstage * STG_BYTES, 0);
            }
            #pragma unroll
            for (int mt = 0; mt < 4; mt++)
                #pragma unroll
                for (int nt = 0; nt < 8; nt++)
                    mma_f16(acc[mt][nt], af[cur][mt], bf[cur][nt]);
            if (ks == 0) {
                // issue next global load after first MMA pack (keeps barrier->MMA path clear)
                if (i + 2 < ITERS) load_slab(i + 2, wstage);
                cp_commit();
            }
        }

        // end of iter: ensure slab i+1 (and i+2) complete + visible; protect stage reuse
        asm volatile("cp.async.wait_group 0;" ::: "memory");
        __syncthreads();
        stage = nstage;
    }

    // epilogue: y = scale * acc + bias
    const float sc = __ldg(scale);
    const int r_lo = lane >> 2;
    #pragma unroll
    for (int mt = 0; mt < 4; mt++) {
        const int m0 = m_cta + wm * 64 + mt * 16 + r_lo;
        #pragma unroll
        for (int nt = 0; nt < 8; nt++) {
            const int n0 = n_cta + wn * 64 + nt * 8 + (lane & 3) * 2;
            const float b0 = __ldg(bias + n0);
            const float b1 = __ldg(bias + n0 + 1);
            float2 v0, v1;
            v0.x = fmaf(sc, acc[mt][nt][0], b0);
            v0.y = fmaf(sc, acc[mt][nt][1], b1);
            v1.x = fmaf(sc, acc[mt][nt][2], b0);
            v1.y = fmaf(sc, acc[mt][nt][3], b1);
            *(float2*)(out + (size_t)m0 * N_TOTAL + n0)       = v0;
            *(float2*)(out + (size_t)(m0 + 8) * N_TOTAL + n0) = v1;
        }
    }
}

// ---------------- host ----------------

extern "C" void kernel_launch(void* const* d_in, const int* in_sizes, int n_in,
                              void* d_out, int out_size)
{
    const float* x     = (const float*)d_in[0];
    const int*   wq    = (const int*)  d_in[1];
    const float* scale = (const float*)d_in[2];
    const float* bias  = (const float*)d_in[3];
    float*       out   = (float*)d_out;

    convert_all<<<XBLKS + WBLKS, 256>>>((const float4*)x, (const int4*)wq);

    static bool attr_set = false;
    if (!attr_set) {
        cudaFuncSetAttribute(gemm_f16,
                             cudaFuncAttributeMaxDynamicSharedMemorySize, SMEM_TOTAL);
        attr_set = true;
    }

    dim3 grid(N_TOTAL / BN, M_TOTAL / BM);      // (32, 128)
    gemm_f16<<<grid, THREADS, SMEM_TOTAL>>>(scale, bias, out);
}